// round 16
// baseline (speedup 1.0000x reference)
#include <cuda_runtime.h>
#include <math.h>

#define NPTS   8192
#define NB     4
#define NPOINT 409
#define NQ     (NB*NPOINT)   // 1636
#define FPS_CL 4             // FPS cluster size (CTAs per batch)
#define FPS_BLKS (NB*FPS_CL) // 16
#define WORKERS 112          // worker blocks (grid 128 <= 132 resident @ cluster 4)
#define TOTALB  (FPS_BLKS+WORKERS)
#define WWARPS  (WORKERS*8)  // 896 worker warps

// ---- spatial grid (cell 2/28 = 0.0714): repulsion +-1 cell, uniform +-2 cells
#define GD   28
#define GC   (GD*GD*GD)      // 21952 cells per batch
#define CCAP 12

// ---------------- device scratch (no allocations; self-cleaning) ----------------
__device__ double g_rep_part[16];
__device__ double g_uni_part[5][8];
__device__ float  g_newxyz[NQ*3];
__device__ unsigned g_prog[NB];            // FPS progress per batch (release/acquire)
__device__ unsigned g_done, g_bar1, g_bar2;
__device__ int    g_ccnt[NB*GC];
__device__ float4 g_cpts[NB*GC*CCAP];

// Exact (non-FMA-contracted) squared distance, matching XLA's sub->mul->add.
__device__ __forceinline__ float sqdist3(float ax,float ay,float az,
                                         float bx,float by,float bz){
    float dx=__fsub_rn(ax,bx), dy=__fsub_rn(ay,by), dz=__fsub_rn(az,bz);
    return __fadd_rn(__fadd_rn(__fmul_rn(dx,dx),__fmul_rn(dy,dy)),__fmul_rn(dz,dz));
}
__device__ __forceinline__ int cell_of(float v){
    int c = (int)((v + 1.0f) * 14.0f);
    if (c < 0) c = 0; if (c > GD-1) c = GD-1;
    return c;
}

// ---- cluster / sync helpers ----
__device__ __forceinline__ unsigned int s2u(const void* p){
    unsigned int a;
    asm("{ .reg .u64 t; cvta.to.shared.u64 t, %1; cvt.u32.u64 %0, t; }" : "=r"(a) : "l"(p));
    return a;
}
__device__ __forceinline__ unsigned int ctarank(){
    unsigned int r; asm("mov.u32 %0, %%cluster_ctarank;" : "=r"(r)); return r;
}
__device__ __forceinline__ void slot_store(unsigned int slot_addr, unsigned long long v,
                                           unsigned int rank){
    unsigned int rs;
    asm volatile("mapa.shared::cluster.u32 %0, %1, %2;" : "=r"(rs) : "r"(slot_addr), "r"(rank));
    asm volatile("st.shared::cluster.u64 [%0], %1;" :: "r"(rs), "l"(v) : "memory");
}
__device__ __forceinline__ unsigned long long ld_slot_vol(unsigned int addr){
    unsigned long long v;
    asm volatile("ld.volatile.shared.u64 %0, [%1];" : "=l"(v) : "r"(addr));
    return v;
}
__device__ __forceinline__ void cluster_sync_all(){
    asm volatile("barrier.cluster.arrive.aligned;" ::: "memory");
    asm volatile("barrier.cluster.wait.aligned;"   ::: "memory");
}
__device__ __forceinline__ void worker_bar(unsigned* ctr){
    __threadfence();                      // each thread drains its own stores to L2
    __syncthreads();
    if (threadIdx.x==0){
        atomicAdd(ctr,1u);
        while (atomicAdd(ctr,0u) < (unsigned)WORKERS) __nanosleep(64);
    }
    __syncthreads();
}
__device__ __forceinline__ void prog_publish(unsigned* addr, unsigned v){
    asm volatile("st.release.gpu.u32 [%0], %1;" :: "l"(addr), "r"(v) : "memory");
}
__device__ __forceinline__ unsigned prog_read(unsigned* addr){
    unsigned v;
    asm volatile("ld.acquire.gpu.u32 %0, [%1];" : "=r"(v) : "l"(addr));
    return v;
}

#define UCAP 64

// =====================================================================
// MEGA kernel: blocks 0..15 = FPS (proven tagged-slot DSMEM exchange,
// now also release-publishing per-batch progress for consumers).
// Blocks 16..127 = workers: zero grid -> barrier -> build -> barrier ->
// repulsion -> uniform loss consumed INCREMENTALLY as FPS publishes.
// Last worker finalizes output and resets all statics (replay-safe).
// =====================================================================
__global__ __launch_bounds__(256,1) __cluster_dims__(FPS_CL,1,1)
void mega_kernel(const float* __restrict__ pcd, float* __restrict__ out){
    __shared__ __align__(8) unsigned long long s_slot[2][32]; // FPS parity slots
    __shared__ float4        s_pts[8][UCAP];
    __shared__ int           s_idx[8][UCAP];
    __shared__ int           s_cnt[8];
    __shared__ unsigned char s_sel[8][136];
    __shared__ float         s_acc[5];
    __shared__ float         s_red[8];
    const int tid = threadIdx.x, lane = tid & 31, w = tid >> 5;

    if (blockIdx.x < FPS_BLKS){
        // ---------------- FPS role (R14-proven) ----------------
        const unsigned int rank = ctarank();
        const int b = blockIdx.x / FPS_CL;
        const float* __restrict__ P = pcd + b*NPTS*3;
        const int pbase = (int)rank * (NPTS/FPS_CL);
        const unsigned int slot0 = s2u(&s_slot[0][0]);

        float x[8], y[8], z[8], dmin[8];
        #pragma unroll
        for (int k=0;k<8;k++){
            const int j = pbase + tid + k*256;
            x[k]=P[3*j]; y[k]=P[3*j+1]; z[k]=P[3*j+2];
            dmin[k]=1e10f;
        }
        if (tid < 64) s_slot[tid>>5][tid&31] = 0x1FFull;   // invalid tag 511
        __syncthreads();
        cluster_sync_all();

        float px=P[0], py=P[1], pz=P[2];
        for (int t=0;t<NPOINT;t++){
            if (rank==0 && tid==0){
                const int qi = b*NPOINT + t;
                g_newxyz[3*qi]=px; g_newxyz[3*qi+1]=py; g_newxyz[3*qi+2]=pz;
                prog_publish(&g_prog[b], (unsigned)(t+1));  // release: newxyz visible first
            }
            float bv=-1.f; int bj=0;
            #pragma unroll
            for (int k=0;k<8;k++){
                const float d  = sqdist3(x[k],y[k],z[k],px,py,pz);
                const float nd = fminf(dmin[k], d);
                dmin[k] = nd;
                if (nd > bv){ bv=nd; bj=pbase+tid+k*256; }
            }
            const unsigned vb = __float_as_uint(bv);
            const unsigned mx = __reduce_max_sync(0xffffffffu, vb);
            const unsigned cand = (vb==mx)? (unsigned)bj : 0xffffffffu;
            const unsigned mnj = __reduce_min_sync(0xffffffffu, cand);
            const unsigned tag = (unsigned)t & 511u;
            const int par = t & 1;
            if (lane==0){
                const unsigned long long pk =
                    (((unsigned long long)mx)<<32)
                  | (((unsigned long long)(NPTS-1-(int)mnj))<<9)
                  | (unsigned long long)tag;
                const unsigned int my = slot0 + (unsigned)((par*32 + (int)rank*8 + w)*8);
                #pragma unroll
                for (unsigned int r=0;r<FPS_CL;r++) slot_store(my, pk, r);
            }
            const unsigned int myaddr = slot0 + (unsigned)(par*256) + (unsigned)(lane*8);
            unsigned long long v;
            bool ok;
            do {
                v  = ld_slot_vol(myaddr);
                ok = ((((unsigned)v) ^ tag) & 511u) == 0u;
            } while (!__all_sync(0xffffffffu, ok));
            const unsigned hi = (unsigned)(v>>32), lo = (unsigned)v;
            const unsigned mxhi = __reduce_max_sync(0xffffffffu, hi);
            const unsigned cl   = (hi==mxhi)? lo : 0u;
            const unsigned mxlo = __reduce_max_sync(0xffffffffu, cl);
            const int j = (NPTS-1) - (int)(mxlo>>9);
            px=P[3*j]; py=P[3*j+1]; pz=P[3*j+2];
        }
        cluster_sync_all();
        return;
    }

    // ======================= worker role =======================
    const int wb = blockIdx.x - FPS_BLKS;          // 0..111
    if (tid < 5) s_acc[tid] = 0.f;

    // ---- phase A: zero grid counts ----
    for (int c = wb*256 + tid; c < NB*GC; c += WORKERS*256) g_ccnt[c] = 0;
    worker_bar(&g_bar1);

    // ---- phase B: build grid (atomic scatter) ----
    for (int gp = wb*256 + tid; gp < NB*NPTS; gp += WORKERS*256){
        const int b = gp >> 13, j = gp & (NPTS-1);
        const float x = pcd[(size_t)b*NPTS*3 + 3*j];
        const float y = pcd[(size_t)b*NPTS*3 + 3*j + 1];
        const float z = pcd[(size_t)b*NPTS*3 + 3*j + 2];
        const int cell = b*GC + (cell_of(z)*GD + cell_of(y))*GD + cell_of(x);
        const int slot = atomicAdd(&g_ccnt[cell], 1);
        if (slot < CCAP) g_cpts[(size_t)cell*CCAP + slot] = make_float4(x,y,z,__int_as_float(j));
    }
    worker_bar(&g_bar2);

    // ---- phase C: repulsion (grid ballquery; same-launch reads via __ldcg) ----
    {
        float sthr = 0.f;
        for (int gp = wb*256 + tid; gp < NB*NPTS; gp += WORKERS*256){
            const int b = gp >> 13, i = gp & (NPTS-1);
            const float* __restrict__ P = pcd + b*NPTS*3;
            const float qx=P[3*i], qy=P[3*i+1], qz=P[3*i+2];
            const float R2 = (float)(0.07*0.07);
            int   idxl[20];
            float dl[20];
            int K = 0;
            const int cx = cell_of(qx), cy = cell_of(qy), cz = cell_of(qz);
            for (int dz=-1; dz<=1; dz++){
                const int zz = cz+dz; if (zz<0 || zz>=GD) continue;
                for (int dy=-1; dy<=1; dy++){
                    const int yy = cy+dy; if (yy<0 || yy>=GD) continue;
                    for (int dx=-1; dx<=1; dx++){
                        const int xx = cx+dx; if (xx<0 || xx>=GD) continue;
                        const int cell = b*GC + (zz*GD + yy)*GD + xx;
                        int n = __ldcg(&g_ccnt[cell]); if (n > CCAP) n = CCAP;
                        const float4* __restrict__ cp = &g_cpts[(size_t)cell*CCAP];
                        for (int e=0;e<n;e++){
                            const float4 tp = __ldcg(&cp[e]);
                            const float dd = sqdist3(qx,qy,qz,tp.x,tp.y,tp.z);
                            if (dd <= R2){
                                const int jj = __float_as_int(tp.w);
                                if (K < 20){
                                    int p = K-1;
                                    while (p>=0 && idxl[p]>jj){ idxl[p+1]=idxl[p]; dl[p+1]=dl[p]; p--; }
                                    idxl[p+1]=jj; dl[p+1]=dd; K++;
                                } else if (jj < idxl[19]){
                                    int p = 18;
                                    while (p>=0 && idxl[p]>jj){ idxl[p+1]=idxl[p]; dl[p+1]=dl[p]; p--; }
                                    idxl[p+1]=jj; dl[p+1]=dd;
                                }
                            }
                        }
                    }
                }
            }
            float best[5] = {3.4e38f,3.4e38f,3.4e38f,3.4e38f,3.4e38f};
            float h0 = (K>0)? dl[0] : 0.f;
            for (int k=0;k<K;k++){
                const float dd = dl[k];
                if (dd < best[4]){
                    best[4]=dd;
                    #pragma unroll
                    for (int q=3;q>=0;q--){
                        if (best[q+1]<best[q]){ float tm=best[q]; best[q]=best[q+1]; best[q+1]=tm; }
                    }
                }
            }
            for (int t=K; t<20; t++){
                if (!(h0 < best[4])) break;
                best[4]=h0;
                #pragma unroll
                for (int q=3;q>=0;q--){
                    if (best[q+1]<best[q]){ float tm=best[q]; best[q]=best[q+1]; best[q+1]=tm; }
                }
            }
            const float H2 = (float)(0.03*0.03);
            #pragma unroll
            for (int k=1;k<5;k++){
                const float d5 = fmaxf(best[k], 0.f);
                const float ds = sqrtf(d5);
                const float ww = expf((-d5)/H2);
                sthr = __fadd_rn(sthr, __fsub_rn(0.07f, __fmul_rn(ds,ww)));
            }
        }
        float s = sthr;
        #pragma unroll
        for (int o=16;o;o>>=1) s += __shfl_down_sync(0xffffffffu, s, o);
        if (lane==0) s_red[w] = s;
        __syncthreads();
        if (tid==0){
            float tt=0.f;
            #pragma unroll
            for (int k=0;k<8;k++) tt += s_red[k];
            atomicAdd(&g_rep_part[wb & 15], (double)tt);
        }
    }

    // ---- phase D: uniform loss, consumed as FPS publishes ----
    const double pv[5]  = {0.004,0.008,0.01,0.012,0.016};
    const int    nss[5] = {32,65,81,98,131};
    float r2s[5], expf_[5], denf_[5];
    #pragma unroll
    for (int i=0;i<5;i++){
        double r = sqrt(pv[i]*1.0);
        r2s[i] = (float)(r*r);
        double disk = 3.14159265358979323846 * 1.0 * pv[i] / (double)nss[i];
        double el   = sqrt(2.0*disk/1.732);
        expf_[i] = (float)el;
        denf_[i] = (float)(el + 1e-8);
    }
    const float r2max = r2s[4];
    const int gw = wb*8 + w;                      // global worker warp id
    float wacc[5] = {0.f,0.f,0.f,0.f,0.f};        // lane0 accumulators

    for (int qi = gw; qi < NQ; qi += WWARPS){
        const int b = qi / NPOINT, t = qi % NPOINT;
        if (lane==0){
            while (prog_read(&g_prog[b]) <= (unsigned)t) __nanosleep(256);
        }
        __syncwarp();
        const float qx=__ldcg(&g_newxyz[3*qi]);
        const float qy=__ldcg(&g_newxyz[3*qi+1]);
        const float qz=__ldcg(&g_newxyz[3*qi+2]);

        if (lane==0) s_cnt[w] = 0;
        __syncwarp();
        const int cx = cell_of(qx), cy = cell_of(qy), cz = cell_of(qz);
        for (int cc = lane; cc < 125; cc += 32){
            const int dzc =  cc/25 - 2;
            const int dyc = (cc/5)%5 - 2;
            const int dxc =  cc%5 - 2;
            const int zz = cz+dzc, yy = cy+dyc, xx = cx+dxc;
            if (zz<0 || zz>=GD || yy<0 || yy>=GD || xx<0 || xx>=GD) continue;
            const int cell = b*GC + (zz*GD + yy)*GD + xx;
            int n = __ldcg(&g_ccnt[cell]); if (n > CCAP) n = CCAP;
            const float4* __restrict__ cp = &g_cpts[(size_t)cell*CCAP];
            for (int e=0;e<n;e++){
                const float4 tp = __ldcg(&cp[e]);
                const float dd = sqdist3(tp.x,tp.y,tp.z,qx,qy,qz);
                if (dd <= r2max){
                    const int pos = atomicAdd(&s_cnt[w], 1);
                    if (pos < UCAP){
                        s_pts[w][pos] = make_float4(tp.x,tp.y,tp.z,dd);
                        s_idx[w][pos] = __float_as_int(tp.w);
                    }
                }
            }
        }
        __syncwarp();
        int cnt = s_cnt[w]; if (cnt > UCAP) cnt = UCAP;
        if (lane == 0){                           // sort by point index (exact order)
            for (int a=1;a<cnt;a++){
                const float4 pv4 = s_pts[w][a];
                const int    pi  = s_idx[w][a];
                int p = a-1;
                while (p>=0 && s_idx[w][p] > pi){
                    s_pts[w][p+1] = s_pts[w][p];
                    s_idx[w][p+1] = s_idx[w][p];
                    p--;
                }
                s_pts[w][p+1] = pv4;
                s_idx[w][p+1] = pi;
            }
        }
        __syncwarp();

        #pragma unroll
        for (int i=0;i<5;i++){
            const int   ns  = nss[i];
            const float r2  = r2s[i];
            int K = 0;
            for (int base=0; base<cnt && K<ns; base+=32){
                const int m = base + lane;
                const bool sel = (m < cnt) && (s_pts[w][m].w <= r2);
                const unsigned msk = __ballot_sync(0xffffffffu, sel);
                if (sel){
                    const int pos = K + __popc(msk & ((1u<<lane)-1u));
                    if (pos < ns) s_sel[w][pos] = (unsigned char)m;
                }
                K += __popc(msk);
            }
            if (K > ns) K = ns;
            __syncwarp();

            const int Ppad = ns - K;
            float s = 0.f;
            const float4 p0 = s_pts[w][s_sel[w][0]];
            for (int r = lane; r < K; r += 32){
                const float4 a = s_pts[w][s_sel[w][r]];
                float m1 = 3.4e38f, m2 = 3.4e38f;
                for (int bb=0; bb<K; bb++){
                    const float4 pb = s_pts[w][s_sel[w][bb]];
                    const float dd = sqdist3(a.x,a.y,a.z,pb.x,pb.y,pb.z);
                    if (dd < m1){ m2 = m1; m1 = dd; }
                    else if (dd < m2){ m2 = dd; }
                }
                if (Ppad > 0){
                    const float dd = sqdist3(a.x,a.y,a.z,p0.x,p0.y,p0.z);
                    if (dd < m1){ m2 = m1; m1 = dd; } else if (dd < m2){ m2 = dd; }
                    if (Ppad > 1){
                        if (dd < m1){ m2 = m1; m1 = dd; } else if (dd < m2){ m2 = dd; }
                    }
                }
                const float rud = sqrtf(fabsf(__fadd_rn(m2, 1e-8f)));
                const float dv  = __fsub_rn(rud, expf_[i]);
                s = __fadd_rn(s, __fmul_rn(dv,dv)/denf_[i]);
            }
            if (lane == 0 && Ppad > 0){
                const float rud = sqrtf(fabsf(__fadd_rn(0.f, 1e-8f)));
                const float dv  = __fsub_rn(rud, expf_[i]);
                s = __fadd_rn(s, (float)Ppad * (__fmul_rn(dv,dv)/denf_[i]));
            }
            #pragma unroll
            for (int o=16;o;o>>=1) s += __shfl_down_sync(0xffffffffu, s, o);
            if (lane==0) wacc[i] = __fadd_rn(wacc[i], s);
            __syncwarp();
        }
    }
    if (lane==0){
        #pragma unroll
        for (int i=0;i<5;i++) atomicAdd(&s_acc[i], wacc[i]);
    }
    __threadfence();
    __syncthreads();
    if (tid < 5) atomicAdd(&g_uni_part[tid][wb & 7], (double)s_acc[tid]);

    // ---- finalize: last worker block writes output + resets statics ----
    __threadfence();
    __syncthreads();
    if (tid == 0){
        const unsigned v = atomicAdd(&g_done, 1u);
        if (v == (unsigned)(WORKERS - 1)){
            const double pvf[5]  = {0.004,0.008,0.01,0.012,0.016};
            const int    nssf[5] = {32,65,81,98,131};
            double u = 0.0;
            for (int i=0;i<5;i++){
                double ssum = 0.0;
                #pragma unroll
                for (int k=0;k<8;k++) ssum += __ldcg((const double*)&g_uni_part[i][k]);
                const double m = ssum / ((double)NQ * (double)nssf[i]);
                const double wgt = (pvf[i]*100.0)*(pvf[i]*100.0);
                u += m*wgt;
            }
            u /= 5.0;
            double rsum = 0.0;
            #pragma unroll
            for (int k=0;k<16;k++) rsum += __ldcg((const double*)&g_rep_part[k]);
            out[0] = (float)u;
            out[1] = (float)(rsum / 131072.0);

            // self-clean for next (identical) replay
            for (int k=0;k<16;k++) g_rep_part[k]=0.0;
            for (int i=0;i<5;i++) for (int k=0;k<8;k++) g_uni_part[i][k]=0.0;
            for (int b2=0;b2<NB;b2++) g_prog[b2]=0u;
            g_bar1=0u; g_bar2=0u; g_done=0u;
        }
    }
}

extern "C" void kernel_launch(void* const* d_in, const int* in_sizes, int n_in,
                              void* d_out, int out_size){
    (void)in_sizes; (void)n_in; (void)out_size;
    const float* pcd = (const float*)d_in[0];
    float* out = (float*)d_out;
    mega_kernel<<<TOTALB, 256>>>(pcd, out);   // 16 FPS CTAs (4 clusters) + 112 workers
}